// round 15
// baseline (speedup 1.0000x reference)
#include <cuda_runtime.h>
#include <cuda_bf16.h>
#include <cstdint>

#define MAXN 50000
#define CDIM 128
#define MAXE 800000
#define CAP  64          // per-node bucket capacity (Poisson(16); max<~45)

// Scratch (__device__ globals; no allocations allowed)
__device__ float          g_h[MAXN * CDIM];     // layer-1 gemm out (gather src)
__device__ float          g_h2[MAXN * CDIM];    // layer-2 gemm out (gather src)
__device__ __nv_bfloat16  g_xhi[MAXN * CDIM];   // layer-2 gemm input, hi part
__device__ __nv_bfloat16  g_xlo[MAXN * CDIM];   // layer-2 gemm input, lo part
__device__ __nv_bfloat16  g_w2hi[CDIM * CDIM], g_w2lo[CDIM * CDIM];
__device__ float g_dinv[MAXN];
__device__ int   g_cursor[MAXN];
__device__ int   g_srcs[MAXN * CAP];

// ---------------------------------------------------------------------------
// PTX helpers (sm_80-era: compile for compute_103 without 'a' features)
// ---------------------------------------------------------------------------
__device__ __forceinline__ uint32_t smem_u32(const void* p) {
    uint32_t a;
    asm("{ .reg .u64 t; cvta.to.shared.u64 t, %1; cvt.u32.u64 %0, t; }"
        : "=r"(a) : "l"(p));
    return a;
}
__device__ __forceinline__ void ldm_x4(uint32_t addr, uint32_t* r) {
    asm volatile("ldmatrix.sync.aligned.m8n8.x4.shared.b16 {%0,%1,%2,%3}, [%4];"
                 : "=r"(r[0]), "=r"(r[1]), "=r"(r[2]), "=r"(r[3]) : "r"(addr));
}
__device__ __forceinline__ void ldm_x4_t(uint32_t addr, uint32_t* r) {
    asm volatile("ldmatrix.sync.aligned.m8n8.x4.trans.shared.b16 {%0,%1,%2,%3}, [%4];"
                 : "=r"(r[0]), "=r"(r[1]), "=r"(r[2]), "=r"(r[3]) : "r"(addr));
}
__device__ __forceinline__ void mma_bf16(float* d, const uint32_t* a,
                                         uint32_t b0, uint32_t b1) {
    asm volatile(
        "mma.sync.aligned.m16n8k16.row.col.f32.bf16.bf16.f32 "
        "{%0,%1,%2,%3}, {%4,%5,%6,%7}, {%8,%9}, {%0,%1,%2,%3};"
        : "+f"(d[0]), "+f"(d[1]), "+f"(d[2]), "+f"(d[3])
        : "r"(a[0]), "r"(a[1]), "r"(a[2]), "r"(a[3]), "r"(b0), "r"(b1));
}
__device__ __forceinline__ uint32_t pack2(__nv_bfloat16 a, __nv_bfloat16 b) {
    __nv_bfloat162 t; t.x = a; t.y = b;
    return *(uint32_t*)&t;
}
__device__ __forceinline__ void split4(float4 v, uint2& hi, uint2& lo) {
    __nv_bfloat16 hx = __float2bfloat16_rn(v.x), hy = __float2bfloat16_rn(v.y);
    __nv_bfloat16 hz = __float2bfloat16_rn(v.z), hw = __float2bfloat16_rn(v.w);
    hi = make_uint2(pack2(hx, hy), pack2(hz, hw));
    lo = make_uint2(pack2(__float2bfloat16_rn(v.x - __bfloat162float(hx)),
                          __float2bfloat16_rn(v.y - __bfloat162float(hy))),
                    pack2(__float2bfloat16_rn(v.z - __bfloat162float(hz)),
                          __float2bfloat16_rn(v.w - __bfloat162float(hw))));
}

// ---------------------------------------------------------------------------
// W2 split: fp32 -> bf16 hi/lo (side stream, off critical path)
// ---------------------------------------------------------------------------
__global__ void split_w2_kernel(const float* __restrict__ W2) {
    int idx = blockIdx.x * blockDim.x + threadIdx.x;   // 4096 float4
    if (idx >= CDIM * CDIM / 4) return;
    float4 v = *(const float4*)&W2[(size_t)idx * 4];
    uint2 hi, lo;
    split4(v, hi, lo);
    *(uint2*)&g_w2hi[(size_t)idx * 4] = hi;
    *(uint2*)&g_w2lo[(size_t)idx * 4] = lo;
}

// ---------------------------------------------------------------------------
// PERSISTENT tensor-core GEMM, 2-way bf16 split (hh + hl + lh).
// W hi/lo resident in smem; block loops over 128-row tiles in
// [tileBase, tileBase + tileCnt). CONVERT: in-kernel fp32->bf16 split.
// 256 threads, 8 warps, warp tile 32x64.
// ---------------------------------------------------------------------------
#define PITCH  272
#define SA_HI  0
#define SA_LO  (128 * PITCH)
#define SW_HI  (2 * 128 * PITCH)
#define SW_LO  (SW_HI + 128 * PITCH)
#define SM_TOT (SW_LO + 128 * PITCH)     // 139264 B

template <int CONVERT>
__global__ __launch_bounds__(256, 1) void gemm_persist_kernel(
    const float* __restrict__ Af32, const float* __restrict__ Wf32,
    const __nv_bfloat16* __restrict__ Ahi, const __nv_bfloat16* __restrict__ Alo,
    const __nv_bfloat16* __restrict__ Whi, const __nv_bfloat16* __restrict__ Wlo,
    float* __restrict__ H, int M, int tileBase, int tileCnt)
{
    extern __shared__ __align__(16) char sm[];
    const uint32_t sb = smem_u32(sm);
    const int tid  = threadIdx.x;
    const int wid  = tid >> 5;
    const int lane = tid & 31;

    // ---- W tiles: loaded ONCE, resident for all row tiles ----
    if (CONVERT) {
#pragma unroll
        for (int i = 0; i < 16; i++) {
            int idx = i * 256 + tid;         // 4096 float4
            int row = idx >> 5;
            int c4  = (idx & 31) * 4;
            float4 v = *(const float4*)&Wf32[(size_t)row * CDIM + c4];
            uint2 hi, lo;
            split4(v, hi, lo);
            int off = row * PITCH + c4 * 2;
            *(uint2*)(sm + SW_HI + off) = hi;
            *(uint2*)(sm + SW_LO + off) = lo;
        }
    } else {
#pragma unroll
        for (int i = 0; i < 8; i++) {
            int idx = i * 256 + tid;         // 2048 uint4 per part
            int row = idx >> 4;
            int q   = idx & 15;
            int off = row * PITCH + q * 16;
            *(uint4*)(sm + SW_HI + off) = *(const uint4*)&Whi[(size_t)row * CDIM + q * 8];
            *(uint4*)(sm + SW_LO + off) = *(const uint4*)&Wlo[(size_t)row * CDIM + q * 8];
        }
    }

    const int wm = wid >> 1;            // 0..3 : row band 32*wm
    const int wn = wid & 1;             // 0..1 : col band 64*wn
    const int ar = lane & 15;
    const int ac = (lane >> 4) * 8;
    const int gid = lane >> 2, tig = lane & 3;

    const int tileEnd = tileBase + tileCnt;
    for (int tile = tileBase + blockIdx.x; tile < tileEnd; tile += gridDim.x) {
        const int m0 = tile * 128;
        __syncthreads();   // previous iteration's mainloop done before A refill

        // ---- A tile: 128 rows x 128 k -> hi/lo bf16 ----
        if (CONVERT) {
#pragma unroll
            for (int i = 0; i < 16; i++) {
                int idx = i * 256 + tid;     // 4096 float4
                int row = idx >> 5;
                int c4  = (idx & 31) * 4;
                int gm  = m0 + row;
                float4 v = make_float4(0.f, 0.f, 0.f, 0.f);
                if (gm < M) v = *(const float4*)&Af32[(size_t)gm * CDIM + c4];
                uint2 hi, lo;
                split4(v, hi, lo);
                int off = row * PITCH + c4 * 2;
                *(uint2*)(sm + SA_HI + off) = hi;
                *(uint2*)(sm + SA_LO + off) = lo;
            }
        } else {
#pragma unroll
            for (int i = 0; i < 8; i++) {
                int idx = i * 256 + tid;     // 2048 uint4 per part
                int row = idx >> 4;
                int q   = idx & 15;
                int gm  = m0 + row;
                uint4 vh = make_uint4(0u, 0u, 0u, 0u), vl = vh;
                if (gm < M) {
                    vh = *(const uint4*)&Ahi[(size_t)gm * CDIM + q * 8];
                    vl = *(const uint4*)&Alo[(size_t)gm * CDIM + q * 8];
                }
                int off = row * PITCH + q * 16;
                *(uint4*)(sm + SA_HI + off) = vh;
                *(uint4*)(sm + SA_LO + off) = vl;
            }
        }
        __syncthreads();

        // ---- mainloop ----
        float acc[16][4];
#pragma unroll
        for (int i = 0; i < 16; i++)
#pragma unroll
            for (int j = 0; j < 4; j++) acc[i][j] = 0.0f;

#pragma unroll
        for (int kk = 0; kk < 8; kk++) {
            const int k0 = kk * 16;
            uint32_t ahi[2][4], alo[2][4], bhi[4][4], blo[4][4];
#pragma unroll
            for (int mt = 0; mt < 2; mt++) {
                uint32_t addr = sb + SA_HI + (32 * wm + 16 * mt + ar) * PITCH + (k0 + ac) * 2;
                ldm_x4(addr, ahi[mt]);
                ldm_x4(addr + (SA_LO - SA_HI), alo[mt]);
            }
#pragma unroll
            for (int ng = 0; ng < 4; ng++) {
                uint32_t addr = sb + SW_HI + (k0 + ar) * PITCH + (64 * wn + 16 * ng + ac) * 2;
                ldm_x4_t(addr, bhi[ng]);
                ldm_x4_t(addr + (SW_LO - SW_HI), blo[ng]);
            }
#pragma unroll
            for (int mt = 0; mt < 2; mt++)
#pragma unroll
                for (int na = 0; na < 8; na++) {
                    const int g = na >> 1, hh = (na & 1) * 2;
                    float* d = acc[mt * 8 + na];
                    mma_bf16(d, ahi[mt], bhi[g][hh], bhi[g][hh + 1]);
                    mma_bf16(d, ahi[mt], blo[g][hh], blo[g][hh + 1]);
                    mma_bf16(d, alo[mt], bhi[g][hh], bhi[g][hh + 1]);
                }
        }

        // ---- epilogue (registers only; no smem reads) ----
#pragma unroll
        for (int mt = 0; mt < 2; mt++)
#pragma unroll
            for (int na = 0; na < 8; na++) {
                const float* d = acc[mt * 8 + na];
                int row = m0 + 32 * wm + 16 * mt + gid;
                int col = 64 * wn + 8 * na + 2 * tig;
                if (row < M)
                    *(float2*)&H[(size_t)row * CDIM + col] = make_float2(d[0], d[1]);
                if (row + 8 < M)
                    *(float2*)&H[(size_t)(row + 8) * CDIM + col] = make_float2(d[2], d[3]);
            }
    }
}

// ---------------------------------------------------------------------------
// Bucketed adjacency build
// ---------------------------------------------------------------------------
__global__ void init_kernel(int n) {
    int i = blockIdx.x * blockDim.x + threadIdx.x;
    if (i < n) g_cursor[i] = 0;
}

__global__ void scatter_kernel(const int* __restrict__ ei, int E, int n) {
    int e = blockIdx.x * blockDim.x + threadIdx.x;
    if (e >= E) return;
    int s = ei[e];
    int d = ei[E + e];
    if (s >= 0 && s < n && d >= 0 && d < n) {
        int pos = atomicAdd(&g_cursor[d], 1);
        if (pos < CAP) g_srcs[d * CAP + pos] = s;
    }
}

__global__ void finish_dinv_kernel(int n) {
    int i = blockIdx.x * blockDim.x + threadIdx.x;
    if (i < n) g_dinv[i] = rsqrtf((float)g_cursor[i] + 1.0f);
}

// ---------------------------------------------------------------------------
// Fused bucket aggregate + self-loop + bias + instance-norm + ReLU.
// Node range [node0, nodeEnd). split_out=1: write bf16 hi/lo; 0: fp32.
// ---------------------------------------------------------------------------
__global__ __launch_bounds__(256) void agg_norm_kernel(
    const float* __restrict__ h, const float* __restrict__ bias,
    float* __restrict__ outf, __nv_bfloat16* __restrict__ ohi,
    __nv_bfloat16* __restrict__ olo, int split_out, int node0, int nodeEnd)
{
    int node = node0 + ((blockIdx.x * blockDim.x + threadIdx.x) >> 5);
    int lane = threadIdx.x & 31;
    if (node >= nodeEnd) return;

    const int c = lane * 4;
    const float dd = g_dinv[node];
    const float d2 = dd * dd;

    float4 acc = *(const float4*)&h[(size_t)node * CDIM + c];
    acc.x *= d2; acc.y *= d2; acc.z *= d2; acc.w *= d2;

    const int base = node * CAP;
    int cnt = g_cursor[node];
    if (cnt > CAP) cnt = CAP;

    int t = 0;
    for (; t + 3 < cnt; t += 4) {
        int s0 = g_srcs[base + t + 0];
        int s1 = g_srcs[base + t + 1];
        int s2 = g_srcs[base + t + 2];
        int s3 = g_srcs[base + t + 3];
        float w0 = g_dinv[s0] * dd;
        float w1 = g_dinv[s1] * dd;
        float w2 = g_dinv[s2] * dd;
        float w3 = g_dinv[s3] * dd;
        float4 h0 = *(const float4*)&h[(size_t)s0 * CDIM + c];
        float4 h1 = *(const float4*)&h[(size_t)s1 * CDIM + c];
        float4 h2 = *(const float4*)&h[(size_t)s2 * CDIM + c];
        float4 h3 = *(const float4*)&h[(size_t)s3 * CDIM + c];
        acc.x = fmaf(h0.x, w0, acc.x); acc.y = fmaf(h0.y, w0, acc.y);
        acc.z = fmaf(h0.z, w0, acc.z); acc.w = fmaf(h0.w, w0, acc.w);
        acc.x = fmaf(h1.x, w1, acc.x); acc.y = fmaf(h1.y, w1, acc.y);
        acc.z = fmaf(h1.z, w1, acc.z); acc.w = fmaf(h1.w, w1, acc.w);
        acc.x = fmaf(h2.x, w2, acc.x); acc.y = fmaf(h2.y, w2, acc.y);
        acc.z = fmaf(h2.z, w2, acc.z); acc.w = fmaf(h2.w, w2, acc.w);
        acc.x = fmaf(h3.x, w3, acc.x); acc.y = fmaf(h3.y, w3, acc.y);
        acc.z = fmaf(h3.z, w3, acc.z); acc.w = fmaf(h3.w, w3, acc.w);
    }
    for (; t < cnt; t++) {
        int s0 = g_srcs[base + t];
        float w0 = g_dinv[s0] * dd;
        float4 h0 = *(const float4*)&h[(size_t)s0 * CDIM + c];
        acc.x = fmaf(h0.x, w0, acc.x); acc.y = fmaf(h0.y, w0, acc.y);
        acc.z = fmaf(h0.z, w0, acc.z); acc.w = fmaf(h0.w, w0, acc.w);
    }

    float4 bv = *(const float4*)&bias[c];
    acc.x += bv.x; acc.y += bv.y; acc.z += bv.z; acc.w += bv.w;

    float s  = acc.x + acc.y + acc.z + acc.w;
    float sq = acc.x * acc.x + acc.y * acc.y + acc.z * acc.z + acc.w * acc.w;
#pragma unroll
    for (int o = 16; o > 0; o >>= 1) {
        s  += __shfl_xor_sync(0xFFFFFFFFu, s,  o);
        sq += __shfl_xor_sync(0xFFFFFFFFu, sq, o);
    }
    const float inv128 = 1.0f / 128.0f;
    float mu  = s * inv128;
    float var = sq * inv128 - mu * mu;
    float rs  = rsqrtf(var + 1e-5f);

    float4 o4;
    o4.x = fmaxf(0.f, (acc.x - mu) * rs);
    o4.y = fmaxf(0.f, (acc.y - mu) * rs);
    o4.z = fmaxf(0.f, (acc.z - mu) * rs);
    o4.w = fmaxf(0.f, (acc.w - mu) * rs);

    if (split_out) {
        uint2 hi, lo;
        split4(o4, hi, lo);
        *(uint2*)&ohi[(size_t)node * CDIM + c] = hi;
        *(uint2*)&olo[(size_t)node * CDIM + c] = lo;
    } else {
        *(float4*)&outf[(size_t)node * CDIM + c] = o4;
    }
}

// ---------------------------------------------------------------------------
// Launch
// ---------------------------------------------------------------------------
extern "C" void kernel_launch(void* const* d_in, const int* in_sizes, int n_in,
                              void* d_out, int out_size)
{
    const float* x   = (const float*)d_in[0];
    const int*   ei  = (const int*)d_in[1];      // int32 (JAX x64 disabled)
    const float* W1  = (const float*)d_in[2];
    const float* b1  = (const float*)d_in[3];
    const float* W2  = (const float*)d_in[4];
    const float* b2  = (const float*)d_in[5];
    float*       out = (float*)d_out;

    const int N = in_sizes[0] / CDIM;     // 50000
    const int E = in_sizes[1] / 2;        // 800000

    static float *p_h = nullptr, *p_h2 = nullptr;
    static __nv_bfloat16 *p_xhi, *p_xlo, *p_w2hi, *p_w2lo;
    static cudaStream_t s2;
    static cudaEvent_t ev_fork, ev_join, ev_a, ev_b;
    static int nsm = 148;
    if (p_h == nullptr) {
        cudaGetSymbolAddress((void**)&p_h,    g_h);
        cudaGetSymbolAddress((void**)&p_h2,   g_h2);
        cudaGetSymbolAddress((void**)&p_xhi,  g_xhi);
        cudaGetSymbolAddress((void**)&p_xlo,  g_xlo);
        cudaGetSymbolAddress((void**)&p_w2hi, g_w2hi);
        cudaGetSymbolAddress((void**)&p_w2lo, g_w2lo);
        cudaFuncSetAttribute(gemm_persist_kernel<0>,
                             cudaFuncAttributeMaxDynamicSharedMemorySize, SM_TOT);
        cudaFuncSetAttribute(gemm_persist_kernel<1>,
                             cudaFuncAttributeMaxDynamicSharedMemorySize, SM_TOT);
        cudaStreamCreateWithFlags(&s2, cudaStreamNonBlocking);
        cudaEventCreateWithFlags(&ev_fork, cudaEventDisableTiming);
        cudaEventCreateWithFlags(&ev_join, cudaEventDisableTiming);
        cudaEventCreateWithFlags(&ev_a,    cudaEventDisableTiming);
        cudaEventCreateWithFlags(&ev_b,    cudaEventDisableTiming);
        cudaDeviceGetAttribute(&nsm, cudaDevAttrMultiProcessorCount, 0);
    }

    const int TB = 256;
    const int numTiles = (N + 127) / 128;     // 391
    const int tilesH0  = numTiles / 2;        // 195
    const int tilesH1  = numTiles - tilesH0;  // 196
    const int Nh       = tilesH0 * 128;       // 24960 (node split on tile bound)
    const int N1       = N - Nh;

    dim3 nodeGrid((N + TB - 1) / TB);
    dim3 edgeGrid((E + TB - 1) / TB);
    dim3 gemmGridAll(numTiles < nsm ? numTiles : nsm);
    dim3 gemmGridH0(tilesH0 < nsm ? tilesH0 : nsm);
    dim3 gemmGridH1(tilesH1 < nsm ? tilesH1 : nsm);
    dim3 aggGridAll(((size_t)N * 32 + TB - 1) / TB);
    dim3 aggGridH0(((size_t)Nh * 32 + TB - 1) / TB);
    dim3 aggGridH1(((size_t)N1 * 32 + TB - 1) / TB);

    // ---- fork: W2 split + adjacency build on s2, concurrent with gemm1 ----
    cudaEventRecord(ev_fork, 0);
    cudaStreamWaitEvent(s2, ev_fork, 0);
    split_w2_kernel<<<16, TB, 0, s2>>>(W2);
    init_kernel<<<nodeGrid, TB, 0, s2>>>(N);
    scatter_kernel<<<edgeGrid, TB, 0, s2>>>(ei, E, N);
    finish_dinv_kernel<<<nodeGrid, TB, 0, s2>>>(N);
    cudaEventRecord(ev_join, s2);

    // ---- main: layer-1 persistent GEMM (full, writes g_h) ----
    gemm_persist_kernel<1><<<gemmGridAll, TB, SM_TOT>>>(
        x, W1, nullptr, nullptr, nullptr, nullptr, p_h, N, 0, numTiles);

    // ---- join adjacency; agg1 half0 -> xhi/xlo[0,Nh) ----
    cudaStreamWaitEvent(0, ev_join, 0);
    agg_norm_kernel<<<aggGridH0, TB>>>(p_h, b1, nullptr, p_xhi, p_xlo, 1, 0, Nh);

    // ---- fork gemm2(half0) onto s2 (writes g_h2 — no WAR with agg1) ----
    cudaEventRecord(ev_a, 0);
    cudaStreamWaitEvent(s2, ev_a, 0);
    gemm_persist_kernel<0><<<gemmGridH0, TB, SM_TOT, s2>>>(
        nullptr, nullptr, p_xhi, p_xlo, p_w2hi, p_w2lo, p_h2, N, 0, tilesH0);
    cudaEventRecord(ev_b, s2);

    // ---- main: agg1 half1 (reads g_h — safe), then gemm2 half1 ----
    agg_norm_kernel<<<aggGridH1, TB>>>(p_h, b1, nullptr, p_xhi, p_xlo, 1, Nh, N);
    gemm_persist_kernel<0><<<gemmGridH1, TB, SM_TOT>>>(
        nullptr, nullptr, p_xhi, p_xlo, p_w2hi, p_w2lo, p_h2, N, tilesH0, tilesH1);

    // ---- join gemm2 half0, final aggregate (reads g_h2) ----
    cudaStreamWaitEvent(0, ev_b, 0);
    agg_norm_kernel<<<aggGridAll, TB>>>(p_h2, b2, out, nullptr, nullptr, 0, 0, N);
}

// round 16
// speedup vs baseline: 1.0612x; 1.0612x over previous
#include <cuda_runtime.h>
#include <cuda_bf16.h>
#include <cuda_fp16.h>
#include <cstdint>

#define MAXN 50000
#define CDIM 128
#define MAXE 800000
#define CAP  64          // per-node bucket capacity (Poisson(16); max<~45)

// Scratch (__device__ globals; no allocations allowed)
__device__ __half         g_hf[MAXN * CDIM];    // gemm out, fp16 (gather source)
__device__ __nv_bfloat16  g_xhi[MAXN * CDIM];   // layer-2 gemm input, hi part
__device__ __nv_bfloat16  g_xlo[MAXN * CDIM];   // layer-2 gemm input, lo part
__device__ __nv_bfloat16  g_w2hi[CDIM * CDIM], g_w2lo[CDIM * CDIM];
__device__ float g_dinv[MAXN];
__device__ int   g_cursor[MAXN];
__device__ int   g_srcs[MAXN * CAP];

// ---------------------------------------------------------------------------
// PTX helpers (sm_80-era: compile for compute_103 without 'a' features)
// ---------------------------------------------------------------------------
__device__ __forceinline__ uint32_t smem_u32(const void* p) {
    uint32_t a;
    asm("{ .reg .u64 t; cvta.to.shared.u64 t, %1; cvt.u32.u64 %0, t; }"
        : "=r"(a) : "l"(p));
    return a;
}
__device__ __forceinline__ void ldm_x4(uint32_t addr, uint32_t* r) {
    asm volatile("ldmatrix.sync.aligned.m8n8.x4.shared.b16 {%0,%1,%2,%3}, [%4];"
                 : "=r"(r[0]), "=r"(r[1]), "=r"(r[2]), "=r"(r[3]) : "r"(addr));
}
__device__ __forceinline__ void ldm_x4_t(uint32_t addr, uint32_t* r) {
    asm volatile("ldmatrix.sync.aligned.m8n8.x4.trans.shared.b16 {%0,%1,%2,%3}, [%4];"
                 : "=r"(r[0]), "=r"(r[1]), "=r"(r[2]), "=r"(r[3]) : "r"(addr));
}
__device__ __forceinline__ void mma_bf16(float* d, const uint32_t* a,
                                         uint32_t b0, uint32_t b1) {
    asm volatile(
        "mma.sync.aligned.m16n8k16.row.col.f32.bf16.bf16.f32 "
        "{%0,%1,%2,%3}, {%4,%5,%6,%7}, {%8,%9}, {%0,%1,%2,%3};"
        : "+f"(d[0]), "+f"(d[1]), "+f"(d[2]), "+f"(d[3])
        : "r"(a[0]), "r"(a[1]), "r"(a[2]), "r"(a[3]), "r"(b0), "r"(b1));
}
__device__ __forceinline__ uint32_t pack2(__nv_bfloat16 a, __nv_bfloat16 b) {
    __nv_bfloat162 t; t.x = a; t.y = b;
    return *(uint32_t*)&t;
}
__device__ __forceinline__ void split4(float4 v, uint2& hi, uint2& lo) {
    __nv_bfloat16 hx = __float2bfloat16_rn(v.x), hy = __float2bfloat16_rn(v.y);
    __nv_bfloat16 hz = __float2bfloat16_rn(v.z), hw = __float2bfloat16_rn(v.w);
    hi = make_uint2(pack2(hx, hy), pack2(hz, hw));
    lo = make_uint2(pack2(__float2bfloat16_rn(v.x - __bfloat162float(hx)),
                          __float2bfloat16_rn(v.y - __bfloat162float(hy))),
                    pack2(__float2bfloat16_rn(v.z - __bfloat162float(hz)),
                          __float2bfloat16_rn(v.w - __bfloat162float(hw))));
}
// load 4 contiguous fp16 as float4 (8-byte load)
__device__ __forceinline__ float4 ldh4(const __half* p) {
    uint2 r = *(const uint2*)p;
    float2 f0 = __half22float2(*(__half2*)&r.x);
    float2 f1 = __half22float2(*(__half2*)&r.y);
    return make_float4(f0.x, f0.y, f1.x, f1.y);
}

// ---------------------------------------------------------------------------
// W2 split: fp32 -> bf16 hi/lo (side stream, off critical path)
// ---------------------------------------------------------------------------
__global__ void split_w2_kernel(const float* __restrict__ W2) {
    int idx = blockIdx.x * blockDim.x + threadIdx.x;   // 4096 float4
    if (idx >= CDIM * CDIM / 4) return;
    float4 v = *(const float4*)&W2[(size_t)idx * 4];
    uint2 hi, lo;
    split4(v, hi, lo);
    *(uint2*)&g_w2hi[(size_t)idx * 4] = hi;
    *(uint2*)&g_w2lo[(size_t)idx * 4] = lo;
}

// ---------------------------------------------------------------------------
// PERSISTENT tensor-core GEMM, 2-way bf16 split (hh + hl + lh).
// W hi/lo resident in smem; block loops over 128-row tiles.
// Output H is fp16 (gather source for the aggregation).
// 256 threads, 8 warps, warp tile 32x64. CONVERT: in-kernel fp32->bf16 split.
// ---------------------------------------------------------------------------
#define PITCH  272
#define SA_HI  0
#define SA_LO  (128 * PITCH)
#define SW_HI  (2 * 128 * PITCH)
#define SW_LO  (SW_HI + 128 * PITCH)
#define SM_TOT (SW_LO + 128 * PITCH)     // 139264 B

template <int CONVERT>
__global__ __launch_bounds__(256, 1) void gemm_persist_kernel(
    const float* __restrict__ Af32, const float* __restrict__ Wf32,
    const __nv_bfloat16* __restrict__ Ahi, const __nv_bfloat16* __restrict__ Alo,
    const __nv_bfloat16* __restrict__ Whi, const __nv_bfloat16* __restrict__ Wlo,
    __half* __restrict__ H, int M, int numTiles)
{
    extern __shared__ __align__(16) char sm[];
    const uint32_t sb = smem_u32(sm);
    const int tid  = threadIdx.x;
    const int wid  = tid >> 5;
    const int lane = tid & 31;

    // ---- W tiles: loaded ONCE, resident for all row tiles ----
    if (CONVERT) {
#pragma unroll
        for (int i = 0; i < 16; i++) {
            int idx = i * 256 + tid;         // 4096 float4
            int row = idx >> 5;
            int c4  = (idx & 31) * 4;
            float4 v = *(const float4*)&Wf32[(size_t)row * CDIM + c4];
            uint2 hi, lo;
            split4(v, hi, lo);
            int off = row * PITCH + c4 * 2;
            *(uint2*)(sm + SW_HI + off) = hi;
            *(uint2*)(sm + SW_LO + off) = lo;
        }
    } else {
#pragma unroll
        for (int i = 0; i < 8; i++) {
            int idx = i * 256 + tid;         // 2048 uint4 per part
            int row = idx >> 4;
            int q   = idx & 15;
            int off = row * PITCH + q * 16;
            *(uint4*)(sm + SW_HI + off) = *(const uint4*)&Whi[(size_t)row * CDIM + q * 8];
            *(uint4*)(sm + SW_LO + off) = *(const uint4*)&Wlo[(size_t)row * CDIM + q * 8];
        }
    }

    const int wm = wid >> 1;            // 0..3 : row band 32*wm
    const int wn = wid & 1;             // 0..1 : col band 64*wn
    const int ar = lane & 15;
    const int ac = (lane >> 4) * 8;
    const int gid = lane >> 2, tig = lane & 3;

    for (int tile = blockIdx.x; tile < numTiles; tile += gridDim.x) {
        const int m0 = tile * 128;
        __syncthreads();   // previous iteration's mainloop done before A refill

        // ---- A tile: 128 rows x 128 k -> hi/lo bf16 ----
        if (CONVERT) {
#pragma unroll
            for (int i = 0; i < 16; i++) {
                int idx = i * 256 + tid;     // 4096 float4
                int row = idx >> 5;
                int c4  = (idx & 31) * 4;
                int gm  = m0 + row;
                float4 v = make_float4(0.f, 0.f, 0.f, 0.f);
                if (gm < M) v = *(const float4*)&Af32[(size_t)gm * CDIM + c4];
                uint2 hi, lo;
                split4(v, hi, lo);
                int off = row * PITCH + c4 * 2;
                *(uint2*)(sm + SA_HI + off) = hi;
                *(uint2*)(sm + SA_LO + off) = lo;
            }
        } else {
#pragma unroll
            for (int i = 0; i < 8; i++) {
                int idx = i * 256 + tid;     // 2048 uint4 per part
                int row = idx >> 4;
                int q   = idx & 15;
                int gm  = m0 + row;
                uint4 vh = make_uint4(0u, 0u, 0u, 0u), vl = vh;
                if (gm < M) {
                    vh = *(const uint4*)&Ahi[(size_t)gm * CDIM + q * 8];
                    vl = *(const uint4*)&Alo[(size_t)gm * CDIM + q * 8];
                }
                int off = row * PITCH + q * 16;
                *(uint4*)(sm + SA_HI + off) = vh;
                *(uint4*)(sm + SA_LO + off) = vl;
            }
        }
        __syncthreads();

        // ---- mainloop ----
        float acc[16][4];
#pragma unroll
        for (int i = 0; i < 16; i++)
#pragma unroll
            for (int j = 0; j < 4; j++) acc[i][j] = 0.0f;

#pragma unroll
        for (int kk = 0; kk < 8; kk++) {
            const int k0 = kk * 16;
            uint32_t ahi[2][4], alo[2][4], bhi[4][4], blo[4][4];
#pragma unroll
            for (int mt = 0; mt < 2; mt++) {
                uint32_t addr = sb + SA_HI + (32 * wm + 16 * mt + ar) * PITCH + (k0 + ac) * 2;
                ldm_x4(addr, ahi[mt]);
                ldm_x4(addr + (SA_LO - SA_HI), alo[mt]);
            }
#pragma unroll
            for (int ng = 0; ng < 4; ng++) {
                uint32_t addr = sb + SW_HI + (k0 + ar) * PITCH + (64 * wn + 16 * ng + ac) * 2;
                ldm_x4_t(addr, bhi[ng]);
                ldm_x4_t(addr + (SW_LO - SW_HI), blo[ng]);
            }
#pragma unroll
            for (int mt = 0; mt < 2; mt++)
#pragma unroll
                for (int na = 0; na < 8; na++) {
                    const int g = na >> 1, hh = (na & 1) * 2;
                    float* d = acc[mt * 8 + na];
                    mma_bf16(d, ahi[mt], bhi[g][hh], bhi[g][hh + 1]);
                    mma_bf16(d, ahi[mt], blo[g][hh], blo[g][hh + 1]);
                    mma_bf16(d, alo[mt], bhi[g][hh], bhi[g][hh + 1]);
                }
        }

        // ---- epilogue: fp16 output (halved write traffic) ----
#pragma unroll
        for (int mt = 0; mt < 2; mt++)
#pragma unroll
            for (int na = 0; na < 8; na++) {
                const float* d = acc[mt * 8 + na];
                int row = m0 + 32 * wm + 16 * mt + gid;
                int col = 64 * wn + 8 * na + 2 * tig;
                if (row < M)
                    *(__half2*)&H[(size_t)row * CDIM + col] =
                        __floats2half2_rn(d[0], d[1]);
                if (row + 8 < M)
                    *(__half2*)&H[(size_t)(row + 8) * CDIM + col] =
                        __floats2half2_rn(d[2], d[3]);
            }
    }
}

// ---------------------------------------------------------------------------
// Bucketed adjacency build
// ---------------------------------------------------------------------------
__global__ void init_kernel(int n) {
    int i = blockIdx.x * blockDim.x + threadIdx.x;
    if (i < n) g_cursor[i] = 0;
}

__global__ void scatter_kernel(const int* __restrict__ ei, int E, int n) {
    int e = blockIdx.x * blockDim.x + threadIdx.x;
    if (e >= E) return;
    int s = ei[e];
    int d = ei[E + e];
    if (s >= 0 && s < n && d >= 0 && d < n) {
        int pos = atomicAdd(&g_cursor[d], 1);
        if (pos < CAP) g_srcs[d * CAP + pos] = s;
    }
}

__global__ void finish_dinv_kernel(int n) {
    int i = blockIdx.x * blockDim.x + threadIdx.x;
    if (i < n) g_dinv[i] = rsqrtf((float)g_cursor[i] + 1.0f);
}

// ---------------------------------------------------------------------------
// Fused bucket aggregate + self-loop + bias + instance-norm + ReLU.
// Gathers fp16 h rows (half the bytes of fp32). Accumulation in fp32.
// split_out=1: write bf16 hi/lo (next gemm input); 0: write fp32 out.
// ---------------------------------------------------------------------------
__global__ __launch_bounds__(256) void agg_norm_kernel(
    const __half* __restrict__ h, const float* __restrict__ bias,
    float* __restrict__ outf, __nv_bfloat16* __restrict__ ohi,
    __nv_bfloat16* __restrict__ olo, int split_out, int N)
{
    int node = (blockIdx.x * blockDim.x + threadIdx.x) >> 5;
    int lane = threadIdx.x & 31;
    if (node >= N) return;

    const int c = lane * 4;
    const float dd = g_dinv[node];
    const float d2 = dd * dd;

    float4 acc = ldh4(&h[(size_t)node * CDIM + c]);
    acc.x *= d2; acc.y *= d2; acc.z *= d2; acc.w *= d2;

    const int base = node * CAP;
    int cnt = g_cursor[node];
    if (cnt > CAP) cnt = CAP;

    int t = 0;
    for (; t + 3 < cnt; t += 4) {
        int s0 = g_srcs[base + t + 0];
        int s1 = g_srcs[base + t + 1];
        int s2 = g_srcs[base + t + 2];
        int s3 = g_srcs[base + t + 3];
        float w0 = g_dinv[s0] * dd;
        float w1 = g_dinv[s1] * dd;
        float w2 = g_dinv[s2] * dd;
        float w3 = g_dinv[s3] * dd;
        float4 h0 = ldh4(&h[(size_t)s0 * CDIM + c]);
        float4 h1 = ldh4(&h[(size_t)s1 * CDIM + c]);
        float4 h2 = ldh4(&h[(size_t)s2 * CDIM + c]);
        float4 h3 = ldh4(&h[(size_t)s3 * CDIM + c]);
        acc.x = fmaf(h0.x, w0, acc.x); acc.y = fmaf(h0.y, w0, acc.y);
        acc.z = fmaf(h0.z, w0, acc.z); acc.w = fmaf(h0.w, w0, acc.w);
        acc.x = fmaf(h1.x, w1, acc.x); acc.y = fmaf(h1.y, w1, acc.y);
        acc.z = fmaf(h1.z, w1, acc.z); acc.w = fmaf(h1.w, w1, acc.w);
        acc.x = fmaf(h2.x, w2, acc.x); acc.y = fmaf(h2.y, w2, acc.y);
        acc.z = fmaf(h2.z, w2, acc.z); acc.w = fmaf(h2.w, w2, acc.w);
        acc.x = fmaf(h3.x, w3, acc.x); acc.y = fmaf(h3.y, w3, acc.y);
        acc.z = fmaf(h3.z, w3, acc.z); acc.w = fmaf(h3.w, w3, acc.w);
    }
    for (; t < cnt; t++) {
        int s0 = g_srcs[base + t];
        float w0 = g_dinv[s0] * dd;
        float4 h0 = ldh4(&h[(size_t)s0 * CDIM + c]);
        acc.x = fmaf(h0.x, w0, acc.x); acc.y = fmaf(h0.y, w0, acc.y);
        acc.z = fmaf(h0.z, w0, acc.z); acc.w = fmaf(h0.w, w0, acc.w);
    }

    float4 bv = *(const float4*)&bias[c];
    acc.x += bv.x; acc.y += bv.y; acc.z += bv.z; acc.w += bv.w;

    float s  = acc.x + acc.y + acc.z + acc.w;
    float sq = acc.x * acc.x + acc.y * acc.y + acc.z * acc.z + acc.w * acc.w;
#pragma unroll
    for (int o = 16; o > 0; o >>= 1) {
        s  += __shfl_xor_sync(0xFFFFFFFFu, s,  o);
        sq += __shfl_xor_sync(0xFFFFFFFFu, sq, o);
    }
    const float inv128 = 1.0f / 128.0f;
    float mu  = s * inv128;
    float var = sq * inv128 - mu * mu;
    float rs  = rsqrtf(var + 1e-5f);

    float4 o4;
    o4.x = fmaxf(0.f, (acc.x - mu) * rs);
    o4.y = fmaxf(0.f, (acc.y - mu) * rs);
    o4.z = fmaxf(0.f, (acc.z - mu) * rs);
    o4.w = fmaxf(0.f, (acc.w - mu) * rs);

    if (split_out) {
        uint2 hi, lo;
        split4(o4, hi, lo);
        *(uint2*)&ohi[(size_t)node * CDIM + c] = hi;
        *(uint2*)&olo[(size_t)node * CDIM + c] = lo;
    } else {
        *(float4*)&outf[(size_t)node * CDIM + c] = o4;
    }
}

// ---------------------------------------------------------------------------
// Launch
// ---------------------------------------------------------------------------
extern "C" void kernel_launch(void* const* d_in, const int* in_sizes, int n_in,
                              void* d_out, int out_size)
{
    const float* x   = (const float*)d_in[0];
    const int*   ei  = (const int*)d_in[1];      // int32 (JAX x64 disabled)
    const float* W1  = (const float*)d_in[2];
    const float* b1  = (const float*)d_in[3];
    const float* W2  = (const float*)d_in[4];
    const float* b2  = (const float*)d_in[5];
    float*       out = (float*)d_out;

    const int N = in_sizes[0] / CDIM;     // 50000
    const int E = in_sizes[1] / 2;        // 800000

    static __half *p_hf = nullptr;
    static __nv_bfloat16 *p_xhi, *p_xlo, *p_w2hi, *p_w2lo;
    static cudaStream_t s2;
    static cudaEvent_t ev_fork, ev_join;
    static int nsm = 148;
    if (p_hf == nullptr) {
        cudaGetSymbolAddress((void**)&p_hf,   g_hf);
        cudaGetSymbolAddress((void**)&p_xhi,  g_xhi);
        cudaGetSymbolAddress((void**)&p_xlo,  g_xlo);
        cudaGetSymbolAddress((void**)&p_w2hi, g_w2hi);
        cudaGetSymbolAddress((void**)&p_w2lo, g_w2lo);
        cudaFuncSetAttribute(gemm_persist_kernel<0>,
                             cudaFuncAttributeMaxDynamicSharedMemorySize, SM_TOT);
        cudaFuncSetAttribute(gemm_persist_kernel<1>,
                             cudaFuncAttributeMaxDynamicSharedMemorySize, SM_TOT);
        cudaStreamCreateWithFlags(&s2, cudaStreamNonBlocking);
        cudaEventCreateWithFlags(&ev_fork, cudaEventDisableTiming);
        cudaEventCreateWithFlags(&ev_join, cudaEventDisableTiming);
        cudaDeviceGetAttribute(&nsm, cudaDevAttrMultiProcessorCount, 0);
    }

    const int TB = 256;
    const int numTiles = (N + 127) / 128;     // 391
    dim3 nodeGrid((N + TB - 1) / TB);
    dim3 edgeGrid((E + TB - 1) / TB);
    dim3 gemmGrid(numTiles < nsm ? numTiles : nsm);
    dim3 aggGrid(((size_t)N * 32 + TB - 1) / TB);

    // ---- fork: W2 split + adjacency build on s2, concurrent with gemm1 ----
    cudaEventRecord(ev_fork, 0);
    cudaStreamWaitEvent(s2, ev_fork, 0);
    split_w2_kernel<<<16, TB, 0, s2>>>(W2);
    init_kernel<<<nodeGrid, TB, 0, s2>>>(N);
    scatter_kernel<<<edgeGrid, TB, 0, s2>>>(ei, E, N);
    finish_dinv_kernel<<<nodeGrid, TB, 0, s2>>>(N);
    cudaEventRecord(ev_join, s2);

    // ---- main: layer-1 persistent GEMM (fp32 in, fp16 out) ----
    gemm_persist_kernel<1><<<gemmGrid, TB, SM_TOT>>>(
        x, W1, nullptr, nullptr, nullptr, nullptr, p_hf, N, numTiles);

    // ---- join, then aggregate chain ----
    cudaStreamWaitEvent(0, ev_join, 0);
    agg_norm_kernel<<<aggGrid, TB>>>(p_hf, b1, nullptr, p_xhi, p_xlo, 1, N);
    gemm_persist_kernel<0><<<gemmGrid, TB, SM_TOT>>>(
        nullptr, nullptr, p_xhi, p_xlo, p_w2hi, p_w2lo, p_hf, N, numTiles);
    agg_norm_kernel<<<aggGrid, TB>>>(p_hf, b2, out, nullptr, nullptr, 0, N);
}

// round 17
// speedup vs baseline: 1.1784x; 1.1104x over previous
#include <cuda_runtime.h>
#include <cuda_bf16.h>
#include <cuda_fp16.h>
#include <cstdint>

#define MAXN 50000
#define CDIM 128
#define MAXE 800000
#define CAP  64          // per-node bucket capacity (Poisson(16); max<~45)

// Scratch (__device__ globals; no allocations allowed)
__device__ __half g_hf[MAXN * CDIM];    // gemm out, fp16 (gather source)
__device__ __half g_xf[MAXN * CDIM];    // agg1 out, fp16 (gemm2 A input)
__device__ __half g_w2hi[CDIM * CDIM], g_w2lo[CDIM * CDIM];
__device__ float g_dinv[MAXN];
__device__ int   g_cursor[MAXN];
__device__ int   g_srcs[MAXN * CAP];

// ---------------------------------------------------------------------------
// PTX helpers (sm_80-era: compile for compute_103 without 'a' features)
// ---------------------------------------------------------------------------
__device__ __forceinline__ uint32_t smem_u32(const void* p) {
    uint32_t a;
    asm("{ .reg .u64 t; cvta.to.shared.u64 t, %1; cvt.u32.u64 %0, t; }"
        : "=r"(a) : "l"(p));
    return a;
}
__device__ __forceinline__ void ldm_x4(uint32_t addr, uint32_t* r) {
    asm volatile("ldmatrix.sync.aligned.m8n8.x4.shared.b16 {%0,%1,%2,%3}, [%4];"
                 : "=r"(r[0]), "=r"(r[1]), "=r"(r[2]), "=r"(r[3]) : "r"(addr));
}
__device__ __forceinline__ void ldm_x4_t(uint32_t addr, uint32_t* r) {
    asm volatile("ldmatrix.sync.aligned.m8n8.x4.trans.shared.b16 {%0,%1,%2,%3}, [%4];"
                 : "=r"(r[0]), "=r"(r[1]), "=r"(r[2]), "=r"(r[3]) : "r"(addr));
}
__device__ __forceinline__ void mma_f16(float* d, const uint32_t* a,
                                        uint32_t b0, uint32_t b1) {
    asm volatile(
        "mma.sync.aligned.m16n8k16.row.col.f32.f16.f16.f32 "
        "{%0,%1,%2,%3}, {%4,%5,%6,%7}, {%8,%9}, {%0,%1,%2,%3};"
        : "+f"(d[0]), "+f"(d[1]), "+f"(d[2]), "+f"(d[3])
        : "r"(a[0]), "r"(a[1]), "r"(a[2]), "r"(a[3]), "r"(b0), "r"(b1));
}
__device__ __forceinline__ uint32_t packh2(__half a, __half b) {
    __half2 t; t.x = a; t.y = b;
    return *(uint32_t*)&t;
}
// fp32x4 -> fp16 hi + fp16 lo (hi = rn(v), lo = rn(v - hi); hi+lo ~exact)
__device__ __forceinline__ void split4h(float4 v, uint2& hi, uint2& lo) {
    __half hx = __float2half_rn(v.x), hy = __float2half_rn(v.y);
    __half hz = __float2half_rn(v.z), hw = __float2half_rn(v.w);
    hi = make_uint2(packh2(hx, hy), packh2(hz, hw));
    lo = make_uint2(packh2(__float2half_rn(v.x - __half2float(hx)),
                           __float2half_rn(v.y - __half2float(hy))),
                    packh2(__float2half_rn(v.z - __half2float(hz)),
                           __float2half_rn(v.w - __half2float(hw))));
}
// fp32x4 -> fp16x4 (single)
__device__ __forceinline__ uint2 cvt4h(float4 v) {
    return make_uint2(packh2(__float2half_rn(v.x), __float2half_rn(v.y)),
                      packh2(__float2half_rn(v.z), __float2half_rn(v.w)));
}
// load 4 contiguous fp16 as float4 (8-byte load)
__device__ __forceinline__ float4 ldh4(const __half* p) {
    uint2 r = *(const uint2*)p;
    float2 f0 = __half22float2(*(__half2*)&r.x);
    float2 f1 = __half22float2(*(__half2*)&r.y);
    return make_float4(f0.x, f0.y, f1.x, f1.y);
}

// ---------------------------------------------------------------------------
// W2 split: fp32 -> fp16 hi/lo (side stream, off critical path)
// ---------------------------------------------------------------------------
__global__ void split_w2_kernel(const float* __restrict__ W2) {
    int idx = blockIdx.x * blockDim.x + threadIdx.x;   // 4096 float4
    if (idx >= CDIM * CDIM / 4) return;
    float4 v = *(const float4*)&W2[(size_t)idx * 4];
    uint2 hi, lo;
    split4h(v, hi, lo);
    *(uint2*)&g_w2hi[(size_t)idx * 4] = hi;
    *(uint2*)&g_w2lo[(size_t)idx * 4] = lo;
}

// ---------------------------------------------------------------------------
// PERSISTENT tensor-core GEMM, fp16 mma: D = A * (Whi + Wlo)  (2 MMAs/step).
// A: single fp16 tile. W hi/lo resident in smem. Output H fp16.
// 256 threads, 8 warps, warp tile 32x64. CONVERT: A,W from fp32 in-kernel.
// ---------------------------------------------------------------------------
#define PITCH  272
#define SA     0
#define SW_HI  (128 * PITCH)
#define SW_LO  (2 * 128 * PITCH)
#define SM_TOT (3 * 128 * PITCH)     // 104448 B

template <int CONVERT>
__global__ __launch_bounds__(256, 1) void gemm_persist_kernel(
    const float* __restrict__ Af32, const float* __restrict__ Wf32,
    const __half* __restrict__ Ah,
    const __half* __restrict__ Whi, const __half* __restrict__ Wlo,
    __half* __restrict__ H, int M, int numTiles)
{
    extern __shared__ __align__(16) char sm[];
    const uint32_t sb = smem_u32(sm);
    const int tid  = threadIdx.x;
    const int wid  = tid >> 5;
    const int lane = tid & 31;

    // ---- W tiles: loaded ONCE, resident for all row tiles ----
    if (CONVERT) {
#pragma unroll
        for (int i = 0; i < 16; i++) {
            int idx = i * 256 + tid;         // 4096 float4
            int row = idx >> 5;
            int c4  = (idx & 31) * 4;
            float4 v = *(const float4*)&Wf32[(size_t)row * CDIM + c4];
            uint2 hi, lo;
            split4h(v, hi, lo);
            int off = row * PITCH + c4 * 2;
            *(uint2*)(sm + SW_HI + off) = hi;
            *(uint2*)(sm + SW_LO + off) = lo;
        }
    } else {
#pragma unroll
        for (int i = 0; i < 8; i++) {
            int idx = i * 256 + tid;         // 2048 uint4 per part
            int row = idx >> 4;
            int q   = idx & 15;
            int off = row * PITCH + q * 16;
            *(uint4*)(sm + SW_HI + off) = *(const uint4*)&Whi[(size_t)row * CDIM + q * 8];
            *(uint4*)(sm + SW_LO + off) = *(const uint4*)&Wlo[(size_t)row * CDIM + q * 8];
        }
    }

    const int wm = wid >> 1;            // 0..3 : row band 32*wm
    const int wn = wid & 1;             // 0..1 : col band 64*wn
    const int ar = lane & 15;
    const int ac = (lane >> 4) * 8;
    const int gid = lane >> 2, tig = lane & 3;

    for (int tile = blockIdx.x; tile < numTiles; tile += gridDim.x) {
        const int m0 = tile * 128;
        __syncthreads();   // previous iteration's mainloop done before A refill

        // ---- A tile: 128 rows x 128 k, single fp16 ----
        if (CONVERT) {
#pragma unroll
            for (int i = 0; i < 16; i++) {
                int idx = i * 256 + tid;     // 4096 float4
                int row = idx >> 5;
                int c4  = (idx & 31) * 4;
                int gm  = m0 + row;
                float4 v = make_float4(0.f, 0.f, 0.f, 0.f);
                if (gm < M) v = *(const float4*)&Af32[(size_t)gm * CDIM + c4];
                *(uint2*)(sm + SA + row * PITCH + c4 * 2) = cvt4h(v);
            }
        } else {
#pragma unroll
            for (int i = 0; i < 8; i++) {
                int idx = i * 256 + tid;     // 2048 uint4
                int row = idx >> 4;
                int q   = idx & 15;
                int gm  = m0 + row;
                uint4 vh = make_uint4(0u, 0u, 0u, 0u);
                if (gm < M) vh = *(const uint4*)&Ah[(size_t)gm * CDIM + q * 8];
                *(uint4*)(sm + SA + row * PITCH + q * 16) = vh;
            }
        }
        __syncthreads();

        // ---- mainloop: per k16 step, 2 A frags, 8 B frags (hi+lo), 32 MMAs ----
        float acc[16][4];
#pragma unroll
        for (int i = 0; i < 16; i++)
#pragma unroll
            for (int j = 0; j < 4; j++) acc[i][j] = 0.0f;

#pragma unroll
        for (int kk = 0; kk < 8; kk++) {
            const int k0 = kk * 16;
            uint32_t a[2][4], bhi[4][4], blo[4][4];
#pragma unroll
            for (int mt = 0; mt < 2; mt++) {
                uint32_t addr = sb + SA + (32 * wm + 16 * mt + ar) * PITCH + (k0 + ac) * 2;
                ldm_x4(addr, a[mt]);
            }
#pragma unroll
            for (int ng = 0; ng < 4; ng++) {
                uint32_t addr = sb + SW_HI + (k0 + ar) * PITCH + (64 * wn + 16 * ng + ac) * 2;
                ldm_x4_t(addr, bhi[ng]);
                ldm_x4_t(addr + (SW_LO - SW_HI), blo[ng]);
            }
#pragma unroll
            for (int mt = 0; mt < 2; mt++)
#pragma unroll
                for (int na = 0; na < 8; na++) {
                    const int g = na >> 1, hh = (na & 1) * 2;
                    float* d = acc[mt * 8 + na];
                    mma_f16(d, a[mt], bhi[g][hh], bhi[g][hh + 1]);
                    mma_f16(d, a[mt], blo[g][hh], blo[g][hh + 1]);
                }
        }

        // ---- epilogue: fp16 output ----
#pragma unroll
        for (int mt = 0; mt < 2; mt++)
#pragma unroll
            for (int na = 0; na < 8; na++) {
                const float* d = acc[mt * 8 + na];
                int row = m0 + 32 * wm + 16 * mt + gid;
                int col = 64 * wn + 8 * na + 2 * tig;
                if (row < M)
                    *(__half2*)&H[(size_t)row * CDIM + col] =
                        __floats2half2_rn(d[0], d[1]);
                if (row + 8 < M)
                    *(__half2*)&H[(size_t)(row + 8) * CDIM + col] =
                        __floats2half2_rn(d[2], d[3]);
            }
    }
}

// ---------------------------------------------------------------------------
// Bucketed adjacency build
// ---------------------------------------------------------------------------
__global__ void init_kernel(int n) {
    int i = blockIdx.x * blockDim.x + threadIdx.x;
    if (i < n) g_cursor[i] = 0;
}

__global__ void scatter_kernel(const int* __restrict__ ei, int E, int n) {
    int e = blockIdx.x * blockDim.x + threadIdx.x;
    if (e >= E) return;
    int s = ei[e];
    int d = ei[E + e];
    if (s >= 0 && s < n && d >= 0 && d < n) {
        int pos = atomicAdd(&g_cursor[d], 1);
        if (pos < CAP) g_srcs[d * CAP + pos] = s;
    }
}

__global__ void finish_dinv_kernel(int n) {
    int i = blockIdx.x * blockDim.x + threadIdx.x;
    if (i < n) g_dinv[i] = rsqrtf((float)g_cursor[i] + 1.0f);
}

// ---------------------------------------------------------------------------
// Fused bucket aggregate + self-loop + bias + instance-norm + ReLU.
// Gathers fp16 h rows; accumulation in fp32.
// split_out=1: write fp16 (gemm2 A input); 0: write fp32 out.
// ---------------------------------------------------------------------------
__global__ __launch_bounds__(256) void agg_norm_kernel(
    const __half* __restrict__ h, const float* __restrict__ bias,
    float* __restrict__ outf, __half* __restrict__ outh,
    int split_out, int N)
{
    int node = (blockIdx.x * blockDim.x + threadIdx.x) >> 5;
    int lane = threadIdx.x & 31;
    if (node >= N) return;

    const int c = lane * 4;
    const float dd = g_dinv[node];
    const float d2 = dd * dd;

    float4 acc = ldh4(&h[(size_t)node * CDIM + c]);
    acc.x *= d2; acc.y *= d2; acc.z *= d2; acc.w *= d2;

    const int base = node * CAP;
    int cnt = g_cursor[node];
    if (cnt > CAP) cnt = CAP;

    int t = 0;
    for (; t + 3 < cnt; t += 4) {
        int s0 = g_srcs[base + t + 0];
        int s1 = g_srcs[base + t + 1];
        int s2 = g_srcs[base + t + 2];
        int s3 = g_srcs[base + t + 3];
        float w0 = g_dinv[s0] * dd;
        float w1 = g_dinv[s1] * dd;
        float w2 = g_dinv[s2] * dd;
        float w3 = g_dinv[s3] * dd;
        float4 h0 = ldh4(&h[(size_t)s0 * CDIM + c]);
        float4 h1 = ldh4(&h[(size_t)s1 * CDIM + c]);
        float4 h2 = ldh4(&h[(size_t)s2 * CDIM + c]);
        float4 h3 = ldh4(&h[(size_t)s3 * CDIM + c]);
        acc.x = fmaf(h0.x, w0, acc.x); acc.y = fmaf(h0.y, w0, acc.y);
        acc.z = fmaf(h0.z, w0, acc.z); acc.w = fmaf(h0.w, w0, acc.w);
        acc.x = fmaf(h1.x, w1, acc.x); acc.y = fmaf(h1.y, w1, acc.y);
        acc.z = fmaf(h1.z, w1, acc.z); acc.w = fmaf(h1.w, w1, acc.w);
        acc.x = fmaf(h2.x, w2, acc.x); acc.y = fmaf(h2.y, w2, acc.y);
        acc.z = fmaf(h2.z, w2, acc.z); acc.w = fmaf(h2.w, w2, acc.w);
        acc.x = fmaf(h3.x, w3, acc.x); acc.y = fmaf(h3.y, w3, acc.y);
        acc.z = fmaf(h3.z, w3, acc.z); acc.w = fmaf(h3.w, w3, acc.w);
    }
    for (; t < cnt; t++) {
        int s0 = g_srcs[base + t];
        float w0 = g_dinv[s0] * dd;
        float4 h0 = ldh4(&h[(size_t)s0 * CDIM + c]);
        acc.x = fmaf(h0.x, w0, acc.x); acc.y = fmaf(h0.y, w0, acc.y);
        acc.z = fmaf(h0.z, w0, acc.z); acc.w = fmaf(h0.w, w0, acc.w);
    }

    float4 bv = *(const float4*)&bias[c];
    acc.x += bv.x; acc.y += bv.y; acc.z += bv.z; acc.w += bv.w;

    float s  = acc.x + acc.y + acc.z + acc.w;
    float sq = acc.x * acc.x + acc.y * acc.y + acc.z * acc.z + acc.w * acc.w;
#pragma unroll
    for (int o = 16; o > 0; o >>= 1) {
        s  += __shfl_xor_sync(0xFFFFFFFFu, s,  o);
        sq += __shfl_xor_sync(0xFFFFFFFFu, sq, o);
    }
    const float inv128 = 1.0f / 128.0f;
    float mu  = s * inv128;
    float var = sq * inv128 - mu * mu;
    float rs  = rsqrtf(var + 1e-5f);

    float4 o4;
    o4.x = fmaxf(0.f, (acc.x - mu) * rs);
    o4.y = fmaxf(0.f, (acc.y - mu) * rs);
    o4.z = fmaxf(0.f, (acc.z - mu) * rs);
    o4.w = fmaxf(0.f, (acc.w - mu) * rs);

    if (split_out) {
        *(uint2*)&outh[(size_t)node * CDIM + c] = cvt4h(o4);
    } else {
        *(float4*)&outf[(size_t)node * CDIM + c] = o4;
    }
}

// ---------------------------------------------------------------------------
// Launch
// ---------------------------------------------------------------------------
extern "C" void kernel_launch(void* const* d_in, const int* in_sizes, int n_in,
                              void* d_out, int out_size)
{
    const float* x   = (const float*)d_in[0];
    const int*   ei  = (const int*)d_in[1];      // int32 (JAX x64 disabled)
    const float* W1  = (const float*)d_in[2];
    const float* b1  = (const float*)d_in[3];
    const float* W2  = (const float*)d_in[4];
    const float* b2  = (const float*)d_in[5];
    float*       out = (float*)d_out;

    const int N = in_sizes[0] / CDIM;     // 50000
    const int E = in_sizes[1] / 2;        // 800000

    static __half *p_hf = nullptr, *p_xf, *p_w2hi, *p_w2lo;
    static cudaStream_t s2;
    static cudaEvent_t ev_fork, ev_join;
    static int nsm = 148;
    if (p_hf == nullptr) {
        cudaGetSymbolAddress((void**)&p_hf,   g_hf);
        cudaGetSymbolAddress((void**)&p_xf,   g_xf);
        cudaGetSymbolAddress((void**)&p_w2hi, g_w2hi);
        cudaGetSymbolAddress((void**)&p_w2lo, g_w2lo);
        cudaFuncSetAttribute(gemm_persist_kernel<0>,
                             cudaFuncAttributeMaxDynamicSharedMemorySize, SM_TOT);
        cudaFuncSetAttribute(gemm_persist_kernel<1>,
                             cudaFuncAttributeMaxDynamicSharedMemorySize, SM_TOT);
        cudaStreamCreateWithFlags(&s2, cudaStreamNonBlocking);
        cudaEventCreateWithFlags(&ev_fork, cudaEventDisableTiming);
        cudaEventCreateWithFlags(&ev_join, cudaEventDisableTiming);
        cudaDeviceGetAttribute(&nsm, cudaDevAttrMultiProcessorCount, 0);
    }

    const int TB = 256;
    const int numTiles = (N + 127) / 128;     // 391
    dim3 nodeGrid((N + TB - 1) / TB);
    dim3 edgeGrid((E + TB - 1) / TB);
    dim3 gemmGrid(numTiles < nsm ? numTiles : nsm);
    dim3 aggGrid(((size_t)N * 32 + TB - 1) / TB);

    // ---- fork: W2 split + adjacency build on s2, concurrent with gemm1 ----
    cudaEventRecord(ev_fork, 0);
    cudaStreamWaitEvent(s2, ev_fork, 0);
    split_w2_kernel<<<16, TB, 0, s2>>>(W2);
    init_kernel<<<nodeGrid, TB, 0, s2>>>(N);
    scatter_kernel<<<edgeGrid, TB, 0, s2>>>(ei, E, N);
    finish_dinv_kernel<<<nodeGrid, TB, 0, s2>>>(N);
    cudaEventRecord(ev_join, s2);

    // ---- main: layer-1 persistent GEMM (fp32 in, fp16 out) ----
    gemm_persist_kernel<1><<<gemmGrid, TB, SM_TOT>>>(
        x, W1, nullptr, nullptr, nullptr, p_hf, N, numTiles);

    // ---- join, then aggregate chain ----
    cudaStreamWaitEvent(0, ev_join, 0);
    agg_norm_kernel<<<aggGrid, TB>>>(p_hf, b1, nullptr, p_xf, 1, N);
    gemm_persist_kernel<0><<<gemmGrid, TB, SM_TOT>>>(
        nullptr, nullptr, p_xf, p_w2hi, p_w2lo, p_hf, N, numTiles);
    agg_norm_kernel<<<aggGrid, TB>>>(p_hf, b2, out, nullptr, 0, N);
}